// round 8
// baseline (speedup 1.0000x reference)
#include <cuda_runtime.h>
#include <cuda_fp16.h>
#include <math.h>

// ---------------------------------------------------------------------------
// GCN: 3x GCNConv (128->64->64->64) + concat(192) @ Wl(192x8) + log_softmax
// Destination-CSR gather (atomic-free fill), fp16 messages, fp32 accumulate.
// s2 stream: hist->scan1->scan3 [evS] ->fill [evJ] ->w3wl [evW]
// stream 0:  gemm1 ... wait(evS) scaleh (in fill's shadow) ... wait(evJ)
//            gather1(+q1) -> gemm2 -> wait(evW) gather2(+q2,p) -> classify
// Layer 3 folded through classifier: p = dis*(x2 @ (W3@Wl3)).
// Classifier dense parts q1=x1@Wl1, q2=x2@Wl2 computed in gather epilogues.
// ---------------------------------------------------------------------------

#define N_NODES_MAX 50000
#define E_MAX       800000

__device__ float  g_dis [N_NODES_MAX];
__device__ __half g_h   [N_NODES_MAX * 64];
__device__ float  g_x1  [N_NODES_MAX * 64];
__device__ float  g_x2  [N_NODES_MAX * 64];
__device__ float  g_p   [N_NODES_MAX * 8];
__device__ float  g_q1  [N_NODES_MAX * 8];
__device__ float  g_q2  [N_NODES_MAX * 8];
__device__ int    g_cnt [N_NODES_MAX];         // zeroed at end of each call
__device__ int    g_rows[N_NODES_MAX + 1];
__device__ int    g_rank[E_MAX];
__device__ int    g_bsum[256];
__device__ int    g_csr [E_MAX];
__device__ float  g_W34 [64 * 8];
__device__ float  g_c3  [8];

// ---- tiny precompute: W34 = W3 @ Wl[128:192], c3 = bl + b3 @ Wl[128:192] ---
__global__ void k_w3wl(const float* __restrict__ W3, const float* __restrict__ Wl,
                       const float* __restrict__ b3, const float* __restrict__ bl,
                       float* __restrict__ W34, float* __restrict__ c3) {
    int t = threadIdx.x;            // 512 threads: t = k*8 + c
    int k = t >> 3, c = t & 7;
    const float* wl3 = Wl + 128 * 8;
    float s = 0.f;
    #pragma unroll 8
    for (int j = 0; j < 64; j++) s += W3[k * 64 + j] * wl3[j * 8 + c];
    W34[t] = s;
    if (t < 8) {
        float cc = bl[t];
        for (int j = 0; j < 64; j++) cc += b3[j] * wl3[j * 8 + t];
        c3[t] = cc;
    }
}

// ---- CSR build -------------------------------------------------------------
__global__ void k_hist(const int* __restrict__ dst, int* __restrict__ cnt,
                       int* __restrict__ rank, int e) {
    int i = blockIdx.x * blockDim.x + threadIdx.x;
    if (i < e) rank[i] = atomicAdd(&cnt[dst[i]], 1);
}

__device__ __forceinline__ int block_excl_scan256(int v, int tid) {
    __shared__ int ws[8];
    int lane = tid & 31, w = tid >> 5;
    int x = v;
    #pragma unroll
    for (int o = 1; o < 32; o <<= 1) {
        int y = __shfl_up_sync(0xffffffffu, x, o);
        if (lane >= o) x += y;
    }
    if (lane == 31) ws[w] = x;
    __syncthreads();
    if (w == 0) {
        int s = (lane < 8) ? ws[lane] : 0;
        #pragma unroll
        for (int o = 1; o < 8; o <<= 1) {
            int y = __shfl_up_sync(0xffffffffu, s, o);
            if (lane >= o) s += y;
        }
        if (lane < 8) ws[lane] = s;
    }
    __syncthreads();
    int base = (w > 0) ? ws[w - 1] : 0;
    return base + x - v;   // exclusive
}

__global__ void k_scan1(const int* __restrict__ cnt, int* __restrict__ bsum, int n) {
    int tid = threadIdx.x;
    int i = blockIdx.x * 256 + tid;
    int v = (i < n) ? cnt[i] : 0;
    #pragma unroll
    for (int o = 16; o; o >>= 1) v += __shfl_down_sync(0xffffffffu, v, o);
    __shared__ int ws[8];
    if ((tid & 31) == 0) ws[tid >> 5] = v;
    __syncthreads();
    if (tid < 8) {
        int s = ws[tid];
        #pragma unroll
        for (int o = 4; o; o >>= 1) s += __shfl_down_sync(0xffu, s, o);
        if (tid == 0) bsum[blockIdx.x] = s;
    }
}

__global__ void k_scan3(int* __restrict__ cnt, const int* __restrict__ bsum,
                        int* __restrict__ rows, float* __restrict__ dis, int n) {
    int tid = threadIdx.x;
    int bid = blockIdx.x;
    __shared__ int wsb[8];
    __shared__ int sbase;

    int bv = (tid < bid) ? bsum[tid] : 0;       // bid < 256 always
    #pragma unroll
    for (int o = 16; o; o >>= 1) bv += __shfl_down_sync(0xffffffffu, bv, o);
    if ((tid & 31) == 0) wsb[tid >> 5] = bv;
    __syncthreads();
    if (tid == 0) {
        int s = 0;
        #pragma unroll
        for (int w = 0; w < 8; w++) s += wsb[w];
        sbase = s;
    }
    __syncthreads();

    int i = bid * 256 + tid;
    int v = (i < n) ? cnt[i] : 0;
    int e = block_excl_scan256(v, tid) + sbase;
    if (i <= n) rows[i] = e;
    if (i < n) {
        dis[i] = rsqrtf((float)(v + 1));
        cnt[i] = 0;                              // ready for next call
    }
}

__global__ void k_fill(const int* __restrict__ src, const int* __restrict__ dst,
                       const int* __restrict__ rows, const int* __restrict__ rank,
                       int* __restrict__ csr, int e) {
    int i = blockIdx.x * blockDim.x + threadIdx.x;
    if (i < e) csr[__ldg(rows + dst[i]) + rank[i]] = src[i];
}

// ---- scale h by dis (runs in the shadow of k_fill) -------------------------
__global__ void k_scaleh(__half* __restrict__ h, const float* __restrict__ dis,
                         int M) {
    int i = blockIdx.x * blockDim.x + threadIdx.x;
    if (i >= M * 8) return;
    float dd = __ldg(dis + (i >> 3));
    uint4 u = ((const uint4*)h)[i];
    __half2* hp = (__half2*)&u;
    #pragma unroll
    for (int t = 0; t < 4; t++) {
        float2 f = __half22float2(hp[t]);
        hp[t] = __floats2half2_rn(f.x * dd, f.y * dd);
    }
    ((uint4*)h)[i] = u;
}

// ---- GEMM  h = fp16( [dis *] (X @ W) ) -------------------------------------
template <int K, bool SCALE>
__global__ void __launch_bounds__(128, 4)
k_gemm(const float* __restrict__ Xin, const float* __restrict__ W,
       const float* __restrict__ dis, __half* __restrict__ h, int M) {
    constexpr int NCH = K / 32;
    __shared__ float  Xs [128 * 33];
    __shared__ float4 Ws4[32 * 16];

    int tid = threadIdx.x;
    int tx  = tid & 7;
    int ty  = tid >> 3;
    int m0  = blockIdx.x * 128;

    float acc[8][8];
    #pragma unroll
    for (int j = 0; j < 8; j++)
        #pragma unroll
        for (int i = 0; i < 8; i++) acc[j][i] = 0.f;

    const float4* W4 = (const float4*)W;

    #pragma unroll
    for (int ch = 0; ch < NCH; ch++) {
        #pragma unroll
        for (int it = 0; it < 8; it++) {
            int i = tid + it * 128;
            int r = i >> 3, c = i & 7;
            int gr = m0 + r;
            float4 v = make_float4(0.f, 0.f, 0.f, 0.f);
            if (gr < M) v = __ldg((const float4*)(Xin + (size_t)gr * K) + ch * 8 + c);
            float* p = Xs + r * 33 + c * 4;
            p[0] = v.x; p[1] = v.y; p[2] = v.z; p[3] = v.w;
        }
        #pragma unroll
        for (int it = 0; it < 4; it++) {
            int i = tid + it * 128;
            Ws4[i] = __ldg(W4 + ch * 512 + i);
        }
        __syncthreads();

        #pragma unroll 8
        for (int k = 0; k < 32; k++) {
            float a[8];
            #pragma unroll
            for (int j = 0; j < 8; j++) a[j] = Xs[(ty * 8 + j) * 33 + k];
            float4 w0 = Ws4[k * 16 + tx];
            float4 w1 = Ws4[k * 16 + 8 + tx];
            #pragma unroll
            for (int j = 0; j < 8; j++) {
                acc[j][0] += a[j] * w0.x;
                acc[j][1] += a[j] * w0.y;
                acc[j][2] += a[j] * w0.z;
                acc[j][3] += a[j] * w0.w;
                acc[j][4] += a[j] * w1.x;
                acc[j][5] += a[j] * w1.y;
                acc[j][6] += a[j] * w1.z;
                acc[j][7] += a[j] * w1.w;
            }
        }
        if (ch + 1 < NCH) __syncthreads();
    }

    #pragma unroll
    for (int j = 0; j < 8; j++) {
        int gr = m0 + ty * 8 + j;
        if (gr < M) {
            float dd = SCALE ? __ldg(dis + gr) : 1.0f;
            __half2 h0 = __floats2half2_rn(acc[j][0] * dd, acc[j][1] * dd);
            __half2 h1 = __floats2half2_rn(acc[j][2] * dd, acc[j][3] * dd);
            __half2 h2 = __floats2half2_rn(acc[j][4] * dd, acc[j][5] * dd);
            __half2 h3 = __floats2half2_rn(acc[j][6] * dd, acc[j][7] * dd);
            uint2 u0, u1;
            u0.x = *reinterpret_cast<unsigned*>(&h0);
            u0.y = *reinterpret_cast<unsigned*>(&h1);
            u1.x = *reinterpret_cast<unsigned*>(&h2);
            u1.y = *reinterpret_cast<unsigned*>(&h3);
            uint2* hp = (uint2*)(h + (size_t)gr * 64);
            hp[tx]     = u0;
            hp[8 + tx] = u1;
        }
    }
}

// ---- gather helpers (8 lanes per node, 16B per lane) -----------------------
__device__ __forceinline__ void acc_h8(float* acc, uint4 u) {
    __half2* hp = (__half2*)&u;
    #pragma unroll
    for (int t = 0; t < 4; t++) {
        float2 f = __half22float2(hp[t]);
        acc[2 * t]     += f.x;
        acc[2 * t + 1] += f.y;
    }
}

__device__ __forceinline__ void gather_row8(const int* __restrict__ rows,
                                            const int* __restrict__ csr,
                                            const __half* __restrict__ h,
                                            int g, int lane, float* acc) {
    int s0 = __ldg(rows + g);
    int s1 = __ldg(rows + g + 1);
    uint4 us = __ldg((const uint4*)(h + (size_t)g * 64) + lane);
    acc_h8(acc, us);                            // self-loop

    int j = s0;
    for (; j + 4 <= s1; j += 4) {
        int i0 = __ldg(csr + j);
        int i1 = __ldg(csr + j + 1);
        int i2 = __ldg(csr + j + 2);
        int i3 = __ldg(csr + j + 3);
        uint4 u0 = __ldg((const uint4*)(h + (size_t)i0 * 64) + lane);
        uint4 u1 = __ldg((const uint4*)(h + (size_t)i1 * 64) + lane);
        uint4 u2 = __ldg((const uint4*)(h + (size_t)i2 * 64) + lane);
        uint4 u3 = __ldg((const uint4*)(h + (size_t)i3 * 64) + lane);
        acc_h8(acc, u0);
        acc_h8(acc, u1);
        acc_h8(acc, u2);
        acc_h8(acc, u3);
    }
    for (; j < s1; j++) {
        uint4 u0 = __ldg((const uint4*)(h + (size_t)__ldg(csr + j) * 64) + lane);
        acc_h8(acc, u0);
    }
}

// ---- gather + epilogue: x = relu(dis*sum + b); q = x @ Wq; [p = dis*(x@Wp)]
// Wq: 64x8 row-major (class partials for the classifier).
template <bool EMIT_P>
__global__ void __launch_bounds__(256)
k_gatherq(const int* __restrict__ rows, const int* __restrict__ csr,
          const __half* __restrict__ h, const float* __restrict__ dis,
          const float* __restrict__ b, const float* __restrict__ Wq,
          const float* __restrict__ Wp,
          float* __restrict__ xout, float* __restrict__ q,
          float* __restrict__ p, int M) {
    __shared__ float sWq[8 * 64];               // sWq[c*64 + f]
    __shared__ float sWp[EMIT_P ? 8 * 64 : 8];
    int tid = threadIdx.x;
    {
        int i = tid;   sWq[(i & 7) * 64 + (i >> 3)] = __ldg(Wq + i);
        i = tid + 256; sWq[(i & 7) * 64 + (i >> 3)] = __ldg(Wq + i);
        if (EMIT_P) {
            i = tid;       sWp[(i & 7) * 64 + (i >> 3)] = __ldg(Wp + i);
            i = tid + 256; sWp[(i & 7) * 64 + (i >> 3)] = __ldg(Wp + i);
        }
    }
    __syncthreads();

    int g = blockIdx.x * 32 + (tid >> 3);
    if (g >= M) return;
    int lane = tid & 7;
    unsigned mask = 0xFFu << (tid & 0x18);

    float dd = __ldg(dis + g);
    float acc[8];
    #pragma unroll
    for (int t = 0; t < 8; t++) acc[t] = 0.f;
    gather_row8(rows, csr, h, g, lane, acc);

    float4 b0 = __ldg((const float4*)b + 2 * lane);
    float4 b1 = __ldg((const float4*)b + 2 * lane + 1);
    float4 o0, o1;
    o0.x = fmaxf(acc[0] * dd + b0.x, 0.f);
    o0.y = fmaxf(acc[1] * dd + b0.y, 0.f);
    o0.z = fmaxf(acc[2] * dd + b0.z, 0.f);
    o0.w = fmaxf(acc[3] * dd + b0.w, 0.f);
    o1.x = fmaxf(acc[4] * dd + b1.x, 0.f);
    o1.y = fmaxf(acc[5] * dd + b1.y, 0.f);
    o1.z = fmaxf(acc[6] * dd + b1.z, 0.f);
    o1.w = fmaxf(acc[7] * dd + b1.w, 0.f);
    float4* op = (float4*)(xout + (size_t)g * 64);
    op[2 * lane]     = o0;
    op[2 * lane + 1] = o1;

    // q[c] = sum_f x[f]*Wq[f][c]  (this lane holds features lane*8..+7)
    float part[8];
    #pragma unroll
    for (int cc = 0; cc < 8; cc++) {
        const float4* w = (const float4*)(sWq + cc * 64 + lane * 8);
        float4 wa = w[0], wb = w[1];
        part[cc] = o0.x * wa.x + o0.y * wa.y + o0.z * wa.z + o0.w * wa.w
                 + o1.x * wb.x + o1.y * wb.y + o1.z * wb.z + o1.w * wb.w;
    }
    #pragma unroll
    for (int o = 4; o; o >>= 1)
        #pragma unroll
        for (int cc = 0; cc < 8; cc++)
            part[cc] += __shfl_xor_sync(mask, part[cc], o, 8);
    q[(size_t)g * 8 + lane] = part[lane];

    if (EMIT_P) {
        #pragma unroll
        for (int cc = 0; cc < 8; cc++) {
            const float4* w = (const float4*)(sWp + cc * 64 + lane * 8);
            float4 wa = w[0], wb = w[1];
            part[cc] = o0.x * wa.x + o0.y * wa.y + o0.z * wa.z + o0.w * wa.w
                     + o1.x * wb.x + o1.y * wb.y + o1.z * wb.z + o1.w * wb.w;
        }
        #pragma unroll
        for (int o = 4; o; o >>= 1)
            #pragma unroll
            for (int cc = 0; cc < 8; cc++)
                part[cc] += __shfl_xor_sync(mask, part[cc], o, 8);
        p[(size_t)g * 8 + lane] = dd * part[lane];
    }
}

// ---- light classifier: p-gather + q1+q2 + folded layer-3 + log_softmax -----
__global__ void __launch_bounds__(256)
k_classify_p(const int* __restrict__ rows, const int* __restrict__ csr,
             const float* __restrict__ p, const float* __restrict__ dis,
             const float* __restrict__ q1, const float* __restrict__ q2,
             const float* __restrict__ c3, float* __restrict__ out, int M) {
    __shared__ float sc3[8];
    int tid = threadIdx.x;
    if (tid < 8) sc3[tid] = __ldg(c3 + tid);
    __syncthreads();

    int g = blockIdx.x * 32 + (tid >> 3);
    if (g >= M) return;
    int c = tid & 7;
    unsigned mask = 0xFFu << (tid & 0x18);

    int s0 = __ldg(rows + g);
    int s1 = __ldg(rows + g + 1);
    float pc  = __ldg(p + (size_t)g * 8 + c);
    float pc2 = 0.f;
    int j = s0;
    for (; j + 2 <= s1; j += 2) {
        int i0 = __ldg(csr + j);
        int i1 = __ldg(csr + j + 1);
        pc  += __ldg(p + (size_t)i0 * 8 + c);
        pc2 += __ldg(p + (size_t)i1 * 8 + c);
    }
    if (j < s1) pc += __ldg(p + (size_t)__ldg(csr + j) * 8 + c);
    pc += pc2;

    float logit = __ldg(q1 + (size_t)g * 8 + c) + __ldg(q2 + (size_t)g * 8 + c)
                + __ldg(dis + g) * pc + sc3[c];

    float m = logit;
    #pragma unroll
    for (int o = 4; o; o >>= 1) m = fmaxf(m, __shfl_xor_sync(mask, m, o, 8));
    float ex = expf(logit - m);
    float s = ex;
    #pragma unroll
    for (int o = 4; o; o >>= 1) s += __shfl_xor_sync(mask, s, o, 8);
    out[(size_t)g * 8 + c] = logit - (logf(s) + m);
}

// ---------------------------------------------------------------------------
extern "C" void kernel_launch(void* const* d_in, const int* in_sizes, int n_in,
                              void* d_out, int out_size) {
    const float* x  = (const float*)d_in[0];
    const int*   ei = (const int*)  d_in[1];
    const float* W1 = (const float*)d_in[2];
    const float* b1 = (const float*)d_in[3];
    const float* W2 = (const float*)d_in[4];
    const float* b2 = (const float*)d_in[5];
    const float* W3 = (const float*)d_in[6];
    const float* b3 = (const float*)d_in[7];
    const float* Wl = (const float*)d_in[8];
    const float* bl = (const float*)d_in[9];
    float* out = (float*)d_out;

    int N = in_sizes[0] / 128;
    int E = in_sizes[1] / 2;
    const int* src = ei;
    const int* dst = ei + E;

    float *dis, *x1, *x2, *p, *q1, *q2, *W34, *c3;
    __half* h;
    int *cnt, *rows, *rank, *bsum, *csr;
    cudaGetSymbolAddress((void**)&dis,  g_dis);
    cudaGetSymbolAddress((void**)&h,    g_h);
    cudaGetSymbolAddress((void**)&x1,   g_x1);
    cudaGetSymbolAddress((void**)&x2,   g_x2);
    cudaGetSymbolAddress((void**)&p,    g_p);
    cudaGetSymbolAddress((void**)&q1,   g_q1);
    cudaGetSymbolAddress((void**)&q2,   g_q2);
    cudaGetSymbolAddress((void**)&W34,  g_W34);
    cudaGetSymbolAddress((void**)&c3,   g_c3);
    cudaGetSymbolAddress((void**)&cnt,  g_cnt);
    cudaGetSymbolAddress((void**)&rows, g_rows);
    cudaGetSymbolAddress((void**)&rank, g_rank);
    cudaGetSymbolAddress((void**)&bsum, g_bsum);
    cudaGetSymbolAddress((void**)&csr,  g_csr);

    static cudaStream_t s2 = nullptr;
    static cudaEvent_t evF = nullptr, evS = nullptr, evJ = nullptr, evW = nullptr;
    if (s2 == nullptr) {
        cudaStreamCreateWithFlags(&s2, cudaStreamNonBlocking);
        cudaEventCreateWithFlags(&evF, cudaEventDisableTiming);
        cudaEventCreateWithFlags(&evS, cudaEventDisableTiming);
        cudaEventCreateWithFlags(&evJ, cudaEventDisableTiming);
        cudaEventCreateWithFlags(&evW, cudaEventDisableTiming);
    }

    int nb1  = (N + 1 + 255) / 256;
    int eb   = (E + 255) / 256;
    int gb   = (N + 127) / 128;
    int gthb = (N + 31) / 32;
    int shb  = (N * 8 + 255) / 256;

    // ---- fork: CSR build on s2, concurrent with GEMM1 ----------------------
    cudaEventRecord(evF, 0);
    cudaStreamWaitEvent(s2, evF, 0);

    k_hist <<<eb, 256, 0, s2>>>(dst, cnt, rank, E);
    k_scan1<<<nb1, 256, 0, s2>>>(cnt, bsum, N);
    k_scan3<<<nb1, 256, 0, s2>>>(cnt, bsum, rows, dis, N);
    cudaEventRecord(evS, s2);                       // dis + rows ready
    k_fill <<<eb, 256, 0, s2>>>(src, dst, rows, rank, csr, E);
    cudaEventRecord(evJ, s2);                       // csr ready
    k_w3wl <<<1, 512, 0, s2>>>(W3, Wl, b3, bl, W34, c3);
    cudaEventRecord(evW, s2);                       // W34/c3 ready

    // layer-1 GEMM (unscaled h; independent of CSR/dis)
    k_gemm<128, false><<<gb, 128>>>(x, W1, nullptr, h, N);

    // scale h by dis in the shadow of k_fill
    cudaStreamWaitEvent(0, evS, 0);
    k_scaleh<<<shb, 256>>>(h, dis, N);

    cudaStreamWaitEvent(0, evJ, 0);                 // join csr

    // layer 1 aggregate (+ q1 = x1 @ Wl1)
    k_gatherq<false><<<gthb, 256>>>(rows, csr, h, dis, b1, Wl, nullptr,
                                    x1, q1, nullptr, N);

    // layer 2 GEMM + aggregate (+ q2 = x2 @ Wl2, p = dis*(x2 @ W34))
    k_gemm<64, true><<<gb, 128>>>(x1, W2, dis, h, N);
    cudaStreamWaitEvent(0, evW, 0);
    k_gatherq<true><<<gthb, 256>>>(rows, csr, h, dis, b2, Wl + 512, W34,
                                   x2, q2, p, N);

    // classifier with folded layer 3
    k_classify_p<<<gthb, 256>>>(rows, csr, p, dis, q1, q2, c3, out, N);
}